// round 2
// baseline (speedup 1.0000x reference)
#include <cuda_runtime.h>
#include <cstddef>

// ---------------------------------------------------------------------------
// GNN: h = relu(x@W_in+b); 2x SAGEConv(mean-agg) + BN(eval) + relu; out GEMM.
// N=100000 nodes, E=1.6M edges, D_IN=256, H=128, D_OUT=64, fp32 throughout.
//
// Structure:
//   1. zero agg/deg -> deg (atomic) -> rdeg = 1/max(deg,1)
//   2. GEMM_in  : bufA = relu(x @ w_in + b_in)                     [N,128]
//   3. scatter  : agg += bufA[src] at dst  (warp-per-edge atomics)
//   4. GEMM_cmb : bufB = relu(bn((agg*rdeg)@w_l1 + b_l1 + bufA@w_r1))
//   5. zero agg; scatter(bufB); GEMM_cmb -> bufA
//   6. GEMM_out : d_out = bufA @ w_out + b_out                      [N,64]
// BN-affine, 1/deg scaling, bias, relu all fused into GEMM load/epilogue.
// ---------------------------------------------------------------------------

#define MAX_N 100000
#define HID   128

__device__ float g_bufA[(size_t)MAX_N * HID];
__device__ float g_bufB[(size_t)MAX_N * HID];
__device__ float g_agg [(size_t)MAX_N * HID];
__device__ float g_deg [MAX_N];
__device__ float g_rdeg[MAX_N];

// ---------------------------------------------------------------------------
// Small utility kernels
// ---------------------------------------------------------------------------
__global__ void zero_kernel(float* __restrict__ p, int n) {
    int i = blockIdx.x * blockDim.x + threadIdx.x;
    if (i < n) p[i] = 0.0f;
}

__global__ void deg_kernel(const int* __restrict__ dst, float* __restrict__ deg, int E) {
    int e = blockIdx.x * blockDim.x + threadIdx.x;
    if (e < E) atomicAdd(&deg[dst[e]], 1.0f);
}

__global__ void rdeg_kernel(const float* __restrict__ deg, float* __restrict__ rdeg, int n) {
    int i = blockIdx.x * blockDim.x + threadIdx.x;
    if (i < n) rdeg[i] = 1.0f / fmaxf(deg[i], 1.0f);
}

// One warp per edge: 32 lanes x float4 = 128 features.
// Feature table (51MB) and accumulator (51MB) are L2-resident on GB300.
__global__ void scatter_kernel(const float4* __restrict__ h4,
                               const int* __restrict__ src,
                               const int* __restrict__ dst,
                               float* __restrict__ agg, int E) {
    int idx  = blockIdx.x * blockDim.x + threadIdx.x;
    int e    = idx >> 5;
    int lane = idx & 31;
    if (e >= E) return;
    int s = src[e];
    int d = dst[e];
    float4 v = h4[(size_t)s * 32 + lane];
    float* a = agg + (size_t)d * 128 + lane * 4;
    atomicAdd(a + 0, v.x);
    atomicAdd(a + 1, v.y);
    atomicAdd(a + 2, v.z);
    atomicAdd(a + 3, v.w);
}

// ---------------------------------------------------------------------------
// Tiled fp32 GEMM with fused epilogue.
//   C[N, BN] = epilogue( A[N, KTOT] @ W[KTOT, BN] + bias )
//   DUAL:     A columns [0,K0) come from A0 (optionally scaled by rdeg[row]),
//             columns [K0,KTOT) come from A1. W rows likewise from W0 / W1.
//   AFF:      v = v * (gamma[col]*rsqrt(1+eps)) + beta[col]
//   RELU:     v = max(v, 0)
// Block tile 128 x BN, thread tile 8 x (BN/16), 256 threads.
// ---------------------------------------------------------------------------
#define BM 128
#define BK 16

template<int KTOT, int BN, int K0, bool DUAL, bool SCALE_A0, bool RELU, bool AFF>
__global__ void __launch_bounds__(256)
gemm_kernel(const float* __restrict__ A0, const float* __restrict__ A1,
            const float* __restrict__ rdeg,
            const float* __restrict__ W0, const float* __restrict__ W1,
            const float* __restrict__ bias,
            const float* __restrict__ gamma, const float* __restrict__ beta,
            float* __restrict__ C, int Nrows)
{
    constexpr int TM = 8;
    constexpr int TN = BN / 16;
    constexpr int K1 = KTOT - K0;      // stride of A1 (DUAL only)

    __shared__ float As[BK][BM];
    __shared__ float Bs[BK][BN];

    const int tid  = threadIdx.x;
    const int row0 = blockIdx.x * BM;
    const int trow = tid >> 4;         // 0..15
    const int tcol = tid & 15;         // 0..15

    float acc[TM][TN];
#pragma unroll
    for (int i = 0; i < TM; ++i)
#pragma unroll
        for (int j = 0; j < TN; ++j) acc[i][j] = 0.0f;

    for (int kt = 0; kt < KTOT / BK; ++kt) {
        const int kbase = kt * BK;

        // ---- load A tile: 128 rows x 16 cols = 512 float4, 2 per thread ----
#pragma unroll
        for (int i = 0; i < 2; ++i) {
            int f    = tid + i * 256;
            int r    = f >> 2;
            int c4   = (f & 3) * 4;
            int grow = row0 + r;
            int gk   = kbase + c4;
            float4 v = make_float4(0.f, 0.f, 0.f, 0.f);
            if (grow < Nrows) {
                if (!DUAL || gk < K0) {
                    v = *(const float4*)(A0 + (size_t)grow * K0 + gk);
                    if constexpr (SCALE_A0) {
                        float rd = rdeg[grow];
                        v.x *= rd; v.y *= rd; v.z *= rd; v.w *= rd;
                    }
                } else {
                    if constexpr (DUAL) {
                        v = *(const float4*)(A1 + (size_t)grow * K1 + (gk - K0));
                    }
                }
            }
            As[c4 + 0][r] = v.x;
            As[c4 + 1][r] = v.y;
            As[c4 + 2][r] = v.z;
            As[c4 + 3][r] = v.w;
        }

        // ---- load B tile: 16 x BN floats ----
        constexpr int F4R   = BN / 4;            // float4 per W row
        constexpr int B_PER = (BK * BN / 4) / 256;
#pragma unroll
        for (int i = 0; i < B_PER; ++i) {
            int f  = tid + i * 256;
            int kk = f / F4R;
            int c4 = (f % F4R) * 4;
            int gk = kbase + kk;
            const float* Wp;
            if (!DUAL || gk < K0) Wp = W0 + (size_t)gk * BN + c4;
            else                  Wp = W1 + (size_t)(gk - K0) * BN + c4;
            *(float4*)&Bs[kk][c4] = *(const float4*)Wp;
        }
        __syncthreads();

        // ---- compute ----
#pragma unroll
        for (int kk = 0; kk < BK; ++kk) {
            float a[TM], b[TN];
#pragma unroll
            for (int i = 0; i < TM; ++i) a[i] = As[kk][trow * TM + i];
#pragma unroll
            for (int j = 0; j < TN; ++j) b[j] = Bs[kk][tcol * TN + j];
#pragma unroll
            for (int i = 0; i < TM; ++i)
#pragma unroll
                for (int j = 0; j < TN; ++j)
                    acc[i][j] += a[i] * b[j];
        }
        __syncthreads();
    }

    // ---- epilogue: bias (+ BN affine) (+ relu), store ----
#pragma unroll
    for (int j = 0; j < TN; ++j) {
        int col  = tcol * TN + j;
        float bi = bias[col];
        float sc = 1.0f, sh = 0.0f;
        if constexpr (AFF) {
            sc = gamma[col] * rsqrtf(1.0f + 1e-5f);
            sh = beta[col];
        }
#pragma unroll
        for (int i = 0; i < TM; ++i) {
            int grow = row0 + trow * TM + i;
            if (grow < Nrows) {
                float v = acc[i][j] + bi;
                if constexpr (AFF)  v = v * sc + sh;
                if constexpr (RELU) v = fmaxf(v, 0.0f);
                C[(size_t)grow * BN + col] = v;
            }
        }
    }
}

// ---------------------------------------------------------------------------
// Host launcher
// ---------------------------------------------------------------------------
extern "C" void kernel_launch(void* const* d_in, const int* in_sizes, int n_in,
                              void* d_out, int out_size)
{
    const float* x     = (const float*)d_in[0];
    const int*   eidx  = (const int*)  d_in[1];
    const float* w_in  = (const float*)d_in[2];
    const float* b_in  = (const float*)d_in[3];
    const float* w_l1  = (const float*)d_in[4];
    const float* b_l1  = (const float*)d_in[5];
    const float* w_r1  = (const float*)d_in[6];
    const float* g1    = (const float*)d_in[7];
    const float* be1   = (const float*)d_in[8];
    const float* w_l2  = (const float*)d_in[9];
    const float* b_l2  = (const float*)d_in[10];
    const float* w_r2  = (const float*)d_in[11];
    const float* g2    = (const float*)d_in[12];
    const float* be2   = (const float*)d_in[13];
    const float* w_out = (const float*)d_in[14];
    const float* b_out = (const float*)d_in[15];
    float* out = (float*)d_out;

    const int N = in_sizes[0] / 256;
    const int E = in_sizes[1] / 2;
    const int* src = eidx;
    const int* dst = eidx + E;

    float *bufA, *bufB, *agg, *deg, *rdeg;
    cudaGetSymbolAddress((void**)&bufA, g_bufA);
    cudaGetSymbolAddress((void**)&bufB, g_bufB);
    cudaGetSymbolAddress((void**)&agg,  g_agg);
    cudaGetSymbolAddress((void**)&deg,  g_deg);
    cudaGetSymbolAddress((void**)&rdeg, g_rdeg);

    const int NH         = N * HID;
    const int zeroBlocks = (NH + 255) / 256;
    const int nBlocks    = (N + 255) / 256;
    const int eBlocks    = (E + 255) / 256;
    const int gemmBlocks = (N + BM - 1) / BM;
    const long long scatterThreads = (long long)E * 32;
    const int scatBlocks = (int)((scatterThreads + 255) / 256);

    // degree (shared by both layers)
    zero_kernel<<<nBlocks, 256>>>(deg, N);
    deg_kernel<<<eBlocks, 256>>>(dst, deg, E);
    rdeg_kernel<<<nBlocks, 256>>>(deg, rdeg, N);

    // input layer: bufA = relu(x @ w_in + b_in)
    gemm_kernel<256, 128, 256, false, false, true, false><<<gemmBlocks, 256>>>(
        x, nullptr, nullptr, w_in, nullptr, b_in, nullptr, nullptr, bufA, N);

    // SAGE layer 1
    zero_kernel<<<zeroBlocks, 256>>>(agg, NH);
    scatter_kernel<<<scatBlocks, 256>>>((const float4*)bufA, src, dst, agg, E);
    gemm_kernel<256, 128, 128, true, true, true, true><<<gemmBlocks, 256>>>(
        agg, bufA, rdeg, w_l1, w_r1, b_l1, g1, be1, bufB, N);

    // SAGE layer 2
    zero_kernel<<<zeroBlocks, 256>>>(agg, NH);
    scatter_kernel<<<scatBlocks, 256>>>((const float4*)bufB, src, dst, agg, E);
    gemm_kernel<256, 128, 128, true, true, true, true><<<gemmBlocks, 256>>>(
        agg, bufB, rdeg, w_l2, w_r2, b_l2, g2, be2, bufA, N);

    // output layer: out = bufA @ w_out + b_out
    gemm_kernel<128, 64, 128, false, false, false, false><<<gemmBlocks, 256>>>(
        bufA, nullptr, nullptr, w_out, nullptr, b_out, nullptr, nullptr, out, N);
}

// round 3
// speedup vs baseline: 1.8950x; 1.8950x over previous
#include <cuda_runtime.h>
#include <cstddef>

// ---------------------------------------------------------------------------
// GNN: relu(x@W_in+b); 2x SAGEConv(mean) + BN(eval) + relu; out GEMM.
// N=100000, E=1.6M, D_IN=256, H=128, D_OUT=64, fp32.
//
// R2: atomic scatter (205M float atomics/layer) replaced by CSR build +
// warp-per-node gather (L2-resident feature table). Mean (1/deg) fused into
// gather; BN/bias/relu fused into GEMM epilogues.
// ---------------------------------------------------------------------------

#define MAX_N 100000
#define MAX_E 1600000
#define HID   128

__device__ float g_bufA[(size_t)MAX_N * HID];
__device__ float g_bufB[(size_t)MAX_N * HID];
__device__ float g_agg [(size_t)MAX_N * HID];
__device__ float g_rdeg[MAX_N];
__device__ int   g_degi  [MAX_N];
__device__ int   g_cursor[MAX_N];
__device__ int   g_rowptr[MAX_N + 1];
__device__ int   g_csr   [MAX_E];
__device__ int   g_bsum  [1024];

// ---------------------------------------------------------------------------
// CSR build
// ---------------------------------------------------------------------------
__global__ void zero_int_kernel(int* __restrict__ a, int* __restrict__ b, int n) {
    int i = blockIdx.x * blockDim.x + threadIdx.x;
    if (i < n) { a[i] = 0; b[i] = 0; }
}

__global__ void degi_kernel(const int* __restrict__ dst, int* __restrict__ deg, int E) {
    int e = blockIdx.x * blockDim.x + threadIdx.x;
    if (e < E) atomicAdd(&deg[dst[e]], 1);
}

__global__ void rdeg_kernel(const int* __restrict__ deg, float* __restrict__ rdeg, int n) {
    int i = blockIdx.x * blockDim.x + threadIdx.x;
    if (i < n) rdeg[i] = 1.0f / fmaxf((float)deg[i], 1.0f);
}

// level-1 scan: each block handles 1024 elems (256 thr x 4). Writes
// block-local exclusive prescan into rowptr, block total into bsum.
__global__ void scan1_kernel(const int* __restrict__ deg, int* __restrict__ rowptr,
                             int* __restrict__ bsum, int n) {
    __shared__ int warp_tot[8];
    int t = threadIdx.x, lane = t & 31, wid = t >> 5;
    int base = blockIdx.x * 1024 + t * 4;
    int v0 = (base + 0 < n) ? deg[base + 0] : 0;
    int v1 = (base + 1 < n) ? deg[base + 1] : 0;
    int v2 = (base + 2 < n) ? deg[base + 2] : 0;
    int v3 = (base + 3 < n) ? deg[base + 3] : 0;
    int tot = v0 + v1 + v2 + v3;

    // warp inclusive scan of tot
    int inc = tot;
#pragma unroll
    for (int off = 1; off < 32; off <<= 1) {
        int y = __shfl_up_sync(0xFFFFFFFF, inc, off);
        if (lane >= off) inc += y;
    }
    if (lane == 31) warp_tot[wid] = inc;
    __syncthreads();
    if (wid == 0) {
        int w = (lane < 8) ? warp_tot[lane] : 0;
        int wi = w;
#pragma unroll
        for (int off = 1; off < 8; off <<= 1) {
            int y = __shfl_up_sync(0xFFFFFFFF, wi, off);
            if (lane >= off) wi += y;
        }
        if (lane < 8) warp_tot[lane] = wi - w;   // exclusive warp offsets
    }
    __syncthreads();
    int excl = warp_tot[wid] + inc - tot;        // thread's exclusive offset in block

    if (base + 0 < n) rowptr[base + 0] = excl;
    if (base + 1 < n) rowptr[base + 1] = excl + v0;
    if (base + 2 < n) rowptr[base + 2] = excl + v0 + v1;
    if (base + 3 < n) rowptr[base + 3] = excl + v0 + v1 + v2;
    if (t == 255) bsum[blockIdx.x] = warp_tot[7] + inc;   // block total
}

// level-2: single block exclusive scan of block sums (nblk <= 1024)
__global__ void scan2_kernel(int* __restrict__ bsum, int nblk) {
    __shared__ int sh[1024];
    int t = threadIdx.x;                         // 256 threads, 4 each
#pragma unroll
    for (int i = 0; i < 4; ++i) {
        int idx = t + i * 256;
        sh[idx] = (idx < nblk) ? bsum[idx] : 0;
    }
    __syncthreads();
    // serial-ish log scan in shared (Hillis-Steele with barrier, 1024 wide)
    for (int off = 1; off < 1024; off <<= 1) {
        int v[4];
#pragma unroll
        for (int i = 0; i < 4; ++i) {
            int idx = t + i * 256;
            v[i] = (idx >= off) ? sh[idx - off] : 0;
        }
        __syncthreads();
#pragma unroll
        for (int i = 0; i < 4; ++i) sh[t + i * 256] += v[i];
        __syncthreads();
    }
#pragma unroll
    for (int i = 0; i < 4; ++i) {
        int idx = t + i * 256;
        if (idx < nblk) bsum[idx] = (idx == 0) ? 0 : sh[idx - 1];  // exclusive
    }
}

__global__ void scan3_kernel(int* __restrict__ rowptr, const int* __restrict__ bsum,
                             int n, int E) {
    int i = blockIdx.x * blockDim.x + threadIdx.x;
    if (i < n) rowptr[i] += bsum[i >> 10];
    if (i == 0) rowptr[n] = E;
}

__global__ void fill_kernel(const int* __restrict__ src, const int* __restrict__ dst,
                            const int* __restrict__ rowptr, int* __restrict__ cursor,
                            int* __restrict__ csr, int E) {
    int e = blockIdx.x * blockDim.x + threadIdx.x;
    if (e >= E) return;
    int d = dst[e];
    int pos = rowptr[d] + atomicAdd(&cursor[d], 1);
    csr[pos] = src[e];
}

// ---------------------------------------------------------------------------
// Gather: warp per node, 32 lanes x float4 = 128 features. Mean fused.
// ---------------------------------------------------------------------------
__global__ void __launch_bounds__(256)
gather_kernel(const float4* __restrict__ h4, const int* __restrict__ rowptr,
              const int* __restrict__ csr, const float* __restrict__ rdeg,
              float4* __restrict__ out4, int n) {
    int gw   = (blockIdx.x * blockDim.x + threadIdx.x) >> 5;
    int lane = threadIdx.x & 31;
    if (gw >= n) return;
    int s0 = rowptr[gw], s1 = rowptr[gw + 1];
    float4 acc = make_float4(0.f, 0.f, 0.f, 0.f);
    int j = s0;
    for (; j + 4 <= s1; j += 4) {
        int i0 = __ldg(&csr[j]);
        int i1 = __ldg(&csr[j + 1]);
        int i2 = __ldg(&csr[j + 2]);
        int i3 = __ldg(&csr[j + 3]);
        float4 a = h4[(size_t)i0 * 32 + lane];
        float4 b = h4[(size_t)i1 * 32 + lane];
        float4 c = h4[(size_t)i2 * 32 + lane];
        float4 d = h4[(size_t)i3 * 32 + lane];
        acc.x += a.x + b.x + c.x + d.x;
        acc.y += a.y + b.y + c.y + d.y;
        acc.z += a.z + b.z + c.z + d.z;
        acc.w += a.w + b.w + c.w + d.w;
    }
    for (; j < s1; ++j) {
        int i0 = __ldg(&csr[j]);
        float4 a = h4[(size_t)i0 * 32 + lane];
        acc.x += a.x; acc.y += a.y; acc.z += a.z; acc.w += a.w;
    }
    float rd = rdeg[gw];
    acc.x *= rd; acc.y *= rd; acc.z *= rd; acc.w *= rd;
    out4[(size_t)gw * 32 + lane] = acc;
}

// ---------------------------------------------------------------------------
// Tiled fp32 GEMM with fused epilogue (unchanged from R1, minus SCALE_A0 use).
// ---------------------------------------------------------------------------
#define BM 128
#define BK 16

template<int KTOT, int BN, int K0, bool DUAL, bool RELU, bool AFF>
__global__ void __launch_bounds__(256)
gemm_kernel(const float* __restrict__ A0, const float* __restrict__ A1,
            const float* __restrict__ W0, const float* __restrict__ W1,
            const float* __restrict__ bias,
            const float* __restrict__ gamma, const float* __restrict__ beta,
            float* __restrict__ C, int Nrows)
{
    constexpr int TM = 8;
    constexpr int TN = BN / 16;
    constexpr int K1 = KTOT - K0;

    __shared__ float As[BK][BM];
    __shared__ float Bs[BK][BN];

    const int tid  = threadIdx.x;
    const int row0 = blockIdx.x * BM;
    const int trow = tid >> 4;
    const int tcol = tid & 15;

    float acc[TM][TN];
#pragma unroll
    for (int i = 0; i < TM; ++i)
#pragma unroll
        for (int j = 0; j < TN; ++j) acc[i][j] = 0.0f;

    for (int kt = 0; kt < KTOT / BK; ++kt) {
        const int kbase = kt * BK;

#pragma unroll
        for (int i = 0; i < 2; ++i) {
            int f    = tid + i * 256;
            int r    = f >> 2;
            int c4   = (f & 3) * 4;
            int grow = row0 + r;
            int gk   = kbase + c4;
            float4 v = make_float4(0.f, 0.f, 0.f, 0.f);
            if (grow < Nrows) {
                if (!DUAL || gk < K0) {
                    v = *(const float4*)(A0 + (size_t)grow * K0 + gk);
                } else {
                    if constexpr (DUAL) {
                        v = *(const float4*)(A1 + (size_t)grow * K1 + (gk - K0));
                    }
                }
            }
            As[c4 + 0][r] = v.x;
            As[c4 + 1][r] = v.y;
            As[c4 + 2][r] = v.z;
            As[c4 + 3][r] = v.w;
        }

        constexpr int F4R   = BN / 4;
        constexpr int B_PER = (BK * BN / 4) / 256;
#pragma unroll
        for (int i = 0; i < B_PER; ++i) {
            int f  = tid + i * 256;
            int kk = f / F4R;
            int c4 = (f % F4R) * 4;
            int gk = kbase + kk;
            const float* Wp;
            if (!DUAL || gk < K0) Wp = W0 + (size_t)gk * BN + c4;
            else                  Wp = W1 + (size_t)(gk - K0) * BN + c4;
            *(float4*)&Bs[kk][c4] = *(const float4*)Wp;
        }
        __syncthreads();

#pragma unroll
        for (int kk = 0; kk < BK; ++kk) {
            float a[TM], b[TN];
#pragma unroll
            for (int i = 0; i < TM; ++i) a[i] = As[kk][trow * TM + i];
#pragma unroll
            for (int j = 0; j < TN; ++j) b[j] = Bs[kk][tcol * TN + j];
#pragma unroll
            for (int i = 0; i < TM; ++i)
#pragma unroll
                for (int j = 0; j < TN; ++j)
                    acc[i][j] += a[i] * b[j];
        }
        __syncthreads();
    }

#pragma unroll
    for (int j = 0; j < TN; ++j) {
        int col  = tcol * TN + j;
        float bi = bias[col];
        float sc = 1.0f, sh = 0.0f;
        if constexpr (AFF) {
            sc = gamma[col] * rsqrtf(1.0f + 1e-5f);
            sh = beta[col];
        }
#pragma unroll
        for (int i = 0; i < TM; ++i) {
            int grow = row0 + trow * TM + i;
            if (grow < Nrows) {
                float v = acc[i][j] + bi;
                if constexpr (AFF)  v = v * sc + sh;
                if constexpr (RELU) v = fmaxf(v, 0.0f);
                C[(size_t)grow * BN + col] = v;
            }
        }
    }
}

// ---------------------------------------------------------------------------
// Host launcher
// ---------------------------------------------------------------------------
extern "C" void kernel_launch(void* const* d_in, const int* in_sizes, int n_in,
                              void* d_out, int out_size)
{
    const float* x     = (const float*)d_in[0];
    const int*   eidx  = (const int*)  d_in[1];
    const float* w_in  = (const float*)d_in[2];
    const float* b_in  = (const float*)d_in[3];
    const float* w_l1  = (const float*)d_in[4];
    const float* b_l1  = (const float*)d_in[5];
    const float* w_r1  = (const float*)d_in[6];
    const float* g1    = (const float*)d_in[7];
    const float* be1   = (const float*)d_in[8];
    const float* w_l2  = (const float*)d_in[9];
    const float* b_l2  = (const float*)d_in[10];
    const float* w_r2  = (const float*)d_in[11];
    const float* g2    = (const float*)d_in[12];
    const float* be2   = (const float*)d_in[13];
    const float* w_out = (const float*)d_in[14];
    const float* b_out = (const float*)d_in[15];
    float* out = (float*)d_out;

    const int N = in_sizes[0] / 256;
    const int E = in_sizes[1] / 2;
    const int* src = eidx;
    const int* dst = eidx + E;

    float *bufA, *bufB, *agg, *rdeg;
    int *degi, *cursor, *rowptr, *csr, *bsum;
    cudaGetSymbolAddress((void**)&bufA,   g_bufA);
    cudaGetSymbolAddress((void**)&bufB,   g_bufB);
    cudaGetSymbolAddress((void**)&agg,    g_agg);
    cudaGetSymbolAddress((void**)&rdeg,   g_rdeg);
    cudaGetSymbolAddress((void**)&degi,   g_degi);
    cudaGetSymbolAddress((void**)&cursor, g_cursor);
    cudaGetSymbolAddress((void**)&rowptr, g_rowptr);
    cudaGetSymbolAddress((void**)&csr,    g_csr);
    cudaGetSymbolAddress((void**)&bsum,   g_bsum);

    const int nBlocks    = (N + 255) / 256;
    const int eBlocks    = (E + 255) / 256;
    const int gemmBlocks = (N + BM - 1) / BM;
    const int scanBlocks = (N + 1023) / 1024;
    const int gatherBlocks = (int)(((long long)N * 32 + 255) / 256);

    // ---- CSR build (once per call) ----
    zero_int_kernel<<<nBlocks, 256>>>(degi, cursor, N);
    degi_kernel<<<eBlocks, 256>>>(dst, degi, E);
    rdeg_kernel<<<nBlocks, 256>>>(degi, rdeg, N);
    scan1_kernel<<<scanBlocks, 256>>>(degi, rowptr, bsum, N);
    scan2_kernel<<<1, 256>>>(bsum, scanBlocks);
    scan3_kernel<<<nBlocks, 256>>>(rowptr, bsum, N, E);
    fill_kernel<<<eBlocks, 256>>>(src, dst, rowptr, cursor, csr, E);

    // ---- input layer: bufA = relu(x @ w_in + b_in) ----
    gemm_kernel<256, 128, 256, false, true, false><<<gemmBlocks, 256>>>(
        x, nullptr, w_in, nullptr, b_in, nullptr, nullptr, bufA, N);

    // ---- SAGE layer 1 ----
    gather_kernel<<<gatherBlocks, 256>>>((const float4*)bufA, rowptr, csr, rdeg,
                                         (float4*)agg, N);
    gemm_kernel<256, 128, 128, true, true, true><<<gemmBlocks, 256>>>(
        agg, bufA, w_l1, w_r1, b_l1, g1, be1, bufB, N);

    // ---- SAGE layer 2 ----
    gather_kernel<<<gatherBlocks, 256>>>((const float4*)bufB, rowptr, csr, rdeg,
                                         (float4*)agg, N);
    gemm_kernel<256, 128, 128, true, true, true><<<gemmBlocks, 256>>>(
        agg, bufB, w_l2, w_r2, b_l2, g2, be2, bufA, N);

    // ---- output layer ----
    gemm_kernel<128, 64, 128, false, false, false><<<gemmBlocks, 256>>>(
        bufA, nullptr, w_out, nullptr, b_out, nullptr, nullptr, out, N);
}

// round 4
// speedup vs baseline: 1.9656x; 1.0373x over previous
#include <cuda_runtime.h>
#include <cstddef>

// ---------------------------------------------------------------------------
// GNN: relu(x@W_in+b); 2x SAGEConv(mean) + BN(eval) + relu; out GEMM.
// N=100000, E=1.6M, D_IN=256, H=128, D_OUT=64, fp32.
//
// R3: GEMM double-buffered (reg-staged prefetch, 1 barrier/K-tile).
// CSR build + warp-per-node gather unchanged from R2.
// ---------------------------------------------------------------------------

#define MAX_N 100000
#define MAX_E 1600000
#define HID   128

__device__ float g_bufA[(size_t)MAX_N * HID];
__device__ float g_bufB[(size_t)MAX_N * HID];
__device__ float g_agg [(size_t)MAX_N * HID];
__device__ float g_rdeg[MAX_N];
__device__ int   g_degi  [MAX_N];
__device__ int   g_cursor[MAX_N];
__device__ int   g_rowptr[MAX_N + 1];
__device__ int   g_csr   [MAX_E];
__device__ int   g_bsum  [1024];

// ---------------------------------------------------------------------------
// CSR build
// ---------------------------------------------------------------------------
__global__ void zero_int_kernel(int* __restrict__ a, int* __restrict__ b, int n) {
    int i = blockIdx.x * blockDim.x + threadIdx.x;
    if (i < n) { a[i] = 0; b[i] = 0; }
}

__global__ void degi_kernel(const int* __restrict__ dst, int* __restrict__ deg, int E) {
    int e = blockIdx.x * blockDim.x + threadIdx.x;
    if (e < E) atomicAdd(&deg[dst[e]], 1);
}

__global__ void rdeg_kernel(const int* __restrict__ deg, float* __restrict__ rdeg, int n) {
    int i = blockIdx.x * blockDim.x + threadIdx.x;
    if (i < n) rdeg[i] = 1.0f / fmaxf((float)deg[i], 1.0f);
}

__global__ void scan1_kernel(const int* __restrict__ deg, int* __restrict__ rowptr,
                             int* __restrict__ bsum, int n) {
    __shared__ int warp_tot[8];
    int t = threadIdx.x, lane = t & 31, wid = t >> 5;
    int base = blockIdx.x * 1024 + t * 4;
    int v0 = (base + 0 < n) ? deg[base + 0] : 0;
    int v1 = (base + 1 < n) ? deg[base + 1] : 0;
    int v2 = (base + 2 < n) ? deg[base + 2] : 0;
    int v3 = (base + 3 < n) ? deg[base + 3] : 0;
    int tot = v0 + v1 + v2 + v3;

    int inc = tot;
#pragma unroll
    for (int off = 1; off < 32; off <<= 1) {
        int y = __shfl_up_sync(0xFFFFFFFF, inc, off);
        if (lane >= off) inc += y;
    }
    if (lane == 31) warp_tot[wid] = inc;
    __syncthreads();
    if (wid == 0) {
        int w = (lane < 8) ? warp_tot[lane] : 0;
        int wi = w;
#pragma unroll
        for (int off = 1; off < 8; off <<= 1) {
            int y = __shfl_up_sync(0xFFFFFFFF, wi, off);
            if (lane >= off) wi += y;
        }
        if (lane < 8) warp_tot[lane] = wi - w;
    }
    __syncthreads();
    int excl = warp_tot[wid] + inc - tot;

    if (base + 0 < n) rowptr[base + 0] = excl;
    if (base + 1 < n) rowptr[base + 1] = excl + v0;
    if (base + 2 < n) rowptr[base + 2] = excl + v0 + v1;
    if (base + 3 < n) rowptr[base + 3] = excl + v0 + v1 + v2;
    if (t == 255) bsum[blockIdx.x] = warp_tot[7] + inc;
}

__global__ void scan2_kernel(int* __restrict__ bsum, int nblk) {
    __shared__ int sh[1024];
    int t = threadIdx.x;
#pragma unroll
    for (int i = 0; i < 4; ++i) {
        int idx = t + i * 256;
        sh[idx] = (idx < nblk) ? bsum[idx] : 0;
    }
    __syncthreads();
    for (int off = 1; off < 1024; off <<= 1) {
        int v[4];
#pragma unroll
        for (int i = 0; i < 4; ++i) {
            int idx = t + i * 256;
            v[i] = (idx >= off) ? sh[idx - off] : 0;
        }
        __syncthreads();
#pragma unroll
        for (int i = 0; i < 4; ++i) sh[t + i * 256] += v[i];
        __syncthreads();
    }
#pragma unroll
    for (int i = 0; i < 4; ++i) {
        int idx = t + i * 256;
        if (idx < nblk) bsum[idx] = (idx == 0) ? 0 : sh[idx - 1];
    }
}

__global__ void scan3_kernel(int* __restrict__ rowptr, const int* __restrict__ bsum,
                             int n, int E) {
    int i = blockIdx.x * blockDim.x + threadIdx.x;
    if (i < n) rowptr[i] += bsum[i >> 10];
    if (i == 0) rowptr[n] = E;
}

__global__ void fill_kernel(const int* __restrict__ src, const int* __restrict__ dst,
                            const int* __restrict__ rowptr, int* __restrict__ cursor,
                            int* __restrict__ csr, int E) {
    int e = blockIdx.x * blockDim.x + threadIdx.x;
    if (e >= E) return;
    int d = dst[e];
    int pos = rowptr[d] + atomicAdd(&cursor[d], 1);
    csr[pos] = src[e];
}

// ---------------------------------------------------------------------------
// Gather: warp per node, 32 lanes x float4 = 128 features. Mean fused.
// ---------------------------------------------------------------------------
__global__ void __launch_bounds__(256)
gather_kernel(const float4* __restrict__ h4, const int* __restrict__ rowptr,
              const int* __restrict__ csr, const float* __restrict__ rdeg,
              float4* __restrict__ out4, int n) {
    int gw   = (blockIdx.x * blockDim.x + threadIdx.x) >> 5;
    int lane = threadIdx.x & 31;
    if (gw >= n) return;
    int s0 = rowptr[gw], s1 = rowptr[gw + 1];
    float4 acc = make_float4(0.f, 0.f, 0.f, 0.f);
    int j = s0;
    for (; j + 4 <= s1; j += 4) {
        int i0 = __ldg(&csr[j]);
        int i1 = __ldg(&csr[j + 1]);
        int i2 = __ldg(&csr[j + 2]);
        int i3 = __ldg(&csr[j + 3]);
        float4 a = h4[(size_t)i0 * 32 + lane];
        float4 b = h4[(size_t)i1 * 32 + lane];
        float4 c = h4[(size_t)i2 * 32 + lane];
        float4 d = h4[(size_t)i3 * 32 + lane];
        acc.x += a.x + b.x + c.x + d.x;
        acc.y += a.y + b.y + c.y + d.y;
        acc.z += a.z + b.z + c.z + d.z;
        acc.w += a.w + b.w + c.w + d.w;
    }
    for (; j < s1; ++j) {
        int i0 = __ldg(&csr[j]);
        float4 a = h4[(size_t)i0 * 32 + lane];
        acc.x += a.x; acc.y += a.y; acc.z += a.z; acc.w += a.w;
    }
    float rd = rdeg[gw];
    acc.x *= rd; acc.y *= rd; acc.z *= rd; acc.w *= rd;
    out4[(size_t)gw * 32 + lane] = acc;
}

// ---------------------------------------------------------------------------
// Double-buffered tiled fp32 GEMM with fused epilogue.
//   C[N,BN] = epi( A[N,KTOT] @ W[KTOT,BN] + bias ), DUAL splits A/W at K0.
// Block tile 128 x BN, thread tile 8 x (BN/16), 256 threads, 2-stage smem.
// ---------------------------------------------------------------------------
#define BM 128
#define BK 16

template<int KTOT, int BN, int K0, bool DUAL, bool RELU, bool AFF>
__global__ void __launch_bounds__(256, 2)
gemm_kernel(const float* __restrict__ A0, const float* __restrict__ A1,
            const float* __restrict__ W0, const float* __restrict__ W1,
            const float* __restrict__ bias,
            const float* __restrict__ gamma, const float* __restrict__ beta,
            float* __restrict__ C, int Nrows)
{
    constexpr int TM  = 8;
    constexpr int TN  = BN / 16;
    constexpr int K1  = KTOT - K0;
    constexpr int NT  = KTOT / BK;              // K-tiles
    constexpr int F4R   = BN / 4;               // float4 per W row
    constexpr int B_PER = (BK * BN / 4) / 256;  // B float4 per thread

    __shared__ float As[2][BK][BM];
    __shared__ float Bs[2][BK][BN];

    const int tid  = threadIdx.x;
    const int row0 = blockIdx.x * BM;
    const int trow = tid >> 4;
    const int tcol = tid & 15;

    // A-fragment mapping (2 float4 per thread)
    const int ar_r0  = tid >> 2;                // row within tile, frag 0
    const int ar_c   = (tid & 3) * 4;           // k-col within tile
    // B-fragment mapping
    // frag i: f = tid + i*256 ; kk = f / F4R ; c4 = (f % F4R)*4

    float acc[TM][TN];
#pragma unroll
    for (int i = 0; i < TM; ++i)
#pragma unroll
        for (int j = 0; j < TN; ++j) acc[i][j] = 0.0f;

    float4 ar[2];
    float4 br[B_PER];

    auto load_tile = [&](int kt) {
#pragma unroll
        for (int i = 0; i < 2; ++i) {
            int r    = ar_r0 + i * 64;
            int grow = row0 + r;
            int gk   = kt * BK + ar_c;
            float4 v = make_float4(0.f, 0.f, 0.f, 0.f);
            if (grow < Nrows) {
                if (!DUAL || gk < K0)
                    v = *(const float4*)(A0 + (size_t)grow * K0 + gk);
                else if constexpr (DUAL)
                    v = *(const float4*)(A1 + (size_t)grow * K1 + (gk - K0));
            }
            ar[i] = v;
        }
#pragma unroll
        for (int i = 0; i < B_PER; ++i) {
            int f  = tid + i * 256;
            int kk = f / F4R;
            int c4 = (f % F4R) * 4;
            int gk = kt * BK + kk;
            const float* Wp;
            if (!DUAL || gk < K0) Wp = W0 + (size_t)gk * BN + c4;
            else                  Wp = W1 + (size_t)(gk - K0) * BN + c4;
            br[i] = *(const float4*)Wp;
        }
    };

    auto store_tile = [&](int buf) {
#pragma unroll
        for (int i = 0; i < 2; ++i) {
            int r = ar_r0 + i * 64;
            As[buf][ar_c + 0][r] = ar[i].x;
            As[buf][ar_c + 1][r] = ar[i].y;
            As[buf][ar_c + 2][r] = ar[i].z;
            As[buf][ar_c + 3][r] = ar[i].w;
        }
#pragma unroll
        for (int i = 0; i < B_PER; ++i) {
            int f  = tid + i * 256;
            int kk = f / F4R;
            int c4 = (f % F4R) * 4;
            *(float4*)&Bs[buf][kk][c4] = br[i];
        }
    };

    load_tile(0);
    store_tile(0);
    __syncthreads();

    for (int kt = 0; kt < NT; ++kt) {
        const int cur = kt & 1;
        if (kt + 1 < NT) load_tile(kt + 1);      // prefetch (global -> regs)

#pragma unroll
        for (int kk = 0; kk < BK; ++kk) {
            float a[TM], b[TN];
#pragma unroll
            for (int i = 0; i < TM; ++i) a[i] = As[cur][kk][trow * TM + i];
#pragma unroll
            for (int j = 0; j < TN; ++j) b[j] = Bs[cur][kk][tcol * TN + j];
#pragma unroll
            for (int i = 0; i < TM; ++i)
#pragma unroll
                for (int j = 0; j < TN; ++j)
                    acc[i][j] += a[i] * b[j];
        }

        if (kt + 1 < NT) store_tile(cur ^ 1);    // regs -> other buffer
        __syncthreads();
    }

    // epilogue: bias (+ BN affine) (+ relu)
#pragma unroll
    for (int j = 0; j < TN; ++j) {
        int col  = tcol * TN + j;
        float bi = bias[col];
        float sc = 1.0f, sh = 0.0f;
        if constexpr (AFF) {
            sc = gamma[col] * rsqrtf(1.0f + 1e-5f);
            sh = beta[col];
        }
#pragma unroll
        for (int i = 0; i < TM; ++i) {
            int grow = row0 + trow * TM + i;
            if (grow < Nrows) {
                float v = acc[i][j] + bi;
                if constexpr (AFF)  v = v * sc + sh;
                if constexpr (RELU) v = fmaxf(v, 0.0f);
                C[(size_t)grow * BN + col] = v;
            }
        }
    }
}

// ---------------------------------------------------------------------------
// Host launcher
// ---------------------------------------------------------------------------
extern "C" void kernel_launch(void* const* d_in, const int* in_sizes, int n_in,
                              void* d_out, int out_size)
{
    const float* x     = (const float*)d_in[0];
    const int*   eidx  = (const int*)  d_in[1];
    const float* w_in  = (const float*)d_in[2];
    const float* b_in  = (const float*)d_in[3];
    const float* w_l1  = (const float*)d_in[4];
    const float* b_l1  = (const float*)d_in[5];
    const float* w_r1  = (const float*)d_in[6];
    const float* g1    = (const float*)d_in[7];
    const float* be1   = (const float*)d_in[8];
    const float* w_l2  = (const float*)d_in[9];
    const float* b_l2  = (const float*)d_in[10];
    const float* w_r2  = (const float*)d_in[11];
    const float* g2    = (const float*)d_in[12];
    const float* be2   = (const float*)d_in[13];
    const float* w_out = (const float*)d_in[14];
    const float* b_out = (const float*)d_in[15];
    float* out = (float*)d_out;

    const int N = in_sizes[0] / 256;
    const int E = in_sizes[1] / 2;
    const int* src = eidx;
    const int* dst = eidx + E;

    float *bufA, *bufB, *agg, *rdeg;
    int *degi, *cursor, *rowptr, *csr, *bsum;
    cudaGetSymbolAddress((void**)&bufA,   g_bufA);
    cudaGetSymbolAddress((void**)&bufB,   g_bufB);
    cudaGetSymbolAddress((void**)&agg,    g_agg);
    cudaGetSymbolAddress((void**)&rdeg,   g_rdeg);
    cudaGetSymbolAddress((void**)&degi,   g_degi);
    cudaGetSymbolAddress((void**)&cursor, g_cursor);
    cudaGetSymbolAddress((void**)&rowptr, g_rowptr);
    cudaGetSymbolAddress((void**)&csr,    g_csr);
    cudaGetSymbolAddress((void**)&bsum,   g_bsum);

    const int nBlocks    = (N + 255) / 256;
    const int eBlocks    = (E + 255) / 256;
    const int gemmBlocks = (N + BM - 1) / BM;
    const int scanBlocks = (N + 1023) / 1024;
    const int gatherBlocks = (int)(((long long)N * 32 + 255) / 256);

    // ---- CSR build ----
    zero_int_kernel<<<nBlocks, 256>>>(degi, cursor, N);
    degi_kernel<<<eBlocks, 256>>>(dst, degi, E);
    rdeg_kernel<<<nBlocks, 256>>>(degi, rdeg, N);
    scan1_kernel<<<scanBlocks, 256>>>(degi, rowptr, bsum, N);
    scan2_kernel<<<1, 256>>>(bsum, scanBlocks);
    scan3_kernel<<<nBlocks, 256>>>(rowptr, bsum, N, E);
    fill_kernel<<<eBlocks, 256>>>(src, dst, rowptr, cursor, csr, E);

    // ---- input layer: bufA = relu(x @ w_in + b_in) ----
    gemm_kernel<256, 128, 256, false, true, false><<<gemmBlocks, 256>>>(
        x, nullptr, w_in, nullptr, b_in, nullptr, nullptr, bufA, N);

    // ---- SAGE layer 1 ----
    gather_kernel<<<gatherBlocks, 256>>>((const float4*)bufA, rowptr, csr, rdeg,
                                         (float4*)agg, N);
    gemm_kernel<256, 128, 128, true, true, true><<<gemmBlocks, 256>>>(
        agg, bufA, w_l1, w_r1, b_l1, g1, be1, bufB, N);

    // ---- SAGE layer 2 ----
    gather_kernel<<<gatherBlocks, 256>>>((const float4*)bufB, rowptr, csr, rdeg,
                                         (float4*)agg, N);
    gemm_kernel<256, 128, 128, true, true, true><<<gemmBlocks, 256>>>(
        agg, bufB, w_l2, w_r2, b_l2, g2, be2, bufA, N);

    // ---- output layer ----
    gemm_kernel<128, 64, 128, false, false, false><<<gemmBlocks, 256>>>(
        bufA, nullptr, w_out, nullptr, b_out, nullptr, nullptr, out, N);
}

// round 5
// speedup vs baseline: 2.2414x; 1.1403x over previous
#include <cuda_runtime.h>
#include <cstddef>

// ---------------------------------------------------------------------------
// GNN: relu(x@W_in+b); 2x SAGEConv(mean) + BN(eval) + relu; out GEMM.
// N=100000, E=1.6M, D_IN=256, H=128, D_OUT=64, fp32.
//
// R4: GEMM inner loop reworked — LDS.128 fragment reads (kills the 4-way
// bank conflict on B reads), STG.128 epilogue. CSR + gather unchanged.
// ---------------------------------------------------------------------------

#define MAX_N 100000
#define MAX_E 1600000
#define HID   128

__device__ float g_bufA[(size_t)MAX_N * HID];
__device__ float g_bufB[(size_t)MAX_N * HID];
__device__ float g_agg [(size_t)MAX_N * HID];
__device__ float g_rdeg[MAX_N];
__device__ int   g_degi  [MAX_N];
__device__ int   g_cursor[MAX_N];
__device__ int   g_rowptr[MAX_N + 1];
__device__ int   g_csr   [MAX_E];
__device__ int   g_bsum  [1024];

// ---------------------------------------------------------------------------
// CSR build
// ---------------------------------------------------------------------------
__global__ void zero_int_kernel(int* __restrict__ a, int* __restrict__ b, int n) {
    int i = blockIdx.x * blockDim.x + threadIdx.x;
    if (i < n) { a[i] = 0; b[i] = 0; }
}

__global__ void degi_kernel(const int* __restrict__ dst, int* __restrict__ deg, int E) {
    int e = blockIdx.x * blockDim.x + threadIdx.x;
    if (e < E) atomicAdd(&deg[dst[e]], 1);
}

__global__ void rdeg_kernel(const int* __restrict__ deg, float* __restrict__ rdeg, int n) {
    int i = blockIdx.x * blockDim.x + threadIdx.x;
    if (i < n) rdeg[i] = 1.0f / fmaxf((float)deg[i], 1.0f);
}

__global__ void scan1_kernel(const int* __restrict__ deg, int* __restrict__ rowptr,
                             int* __restrict__ bsum, int n) {
    __shared__ int warp_tot[8];
    int t = threadIdx.x, lane = t & 31, wid = t >> 5;
    int base = blockIdx.x * 1024 + t * 4;
    int v0 = (base + 0 < n) ? deg[base + 0] : 0;
    int v1 = (base + 1 < n) ? deg[base + 1] : 0;
    int v2 = (base + 2 < n) ? deg[base + 2] : 0;
    int v3 = (base + 3 < n) ? deg[base + 3] : 0;
    int tot = v0 + v1 + v2 + v3;

    int inc = tot;
#pragma unroll
    for (int off = 1; off < 32; off <<= 1) {
        int y = __shfl_up_sync(0xFFFFFFFF, inc, off);
        if (lane >= off) inc += y;
    }
    if (lane == 31) warp_tot[wid] = inc;
    __syncthreads();
    if (wid == 0) {
        int w = (lane < 8) ? warp_tot[lane] : 0;
        int wi = w;
#pragma unroll
        for (int off = 1; off < 8; off <<= 1) {
            int y = __shfl_up_sync(0xFFFFFFFF, wi, off);
            if (lane >= off) wi += y;
        }
        if (lane < 8) warp_tot[lane] = wi - w;
    }
    __syncthreads();
    int excl = warp_tot[wid] + inc - tot;

    if (base + 0 < n) rowptr[base + 0] = excl;
    if (base + 1 < n) rowptr[base + 1] = excl + v0;
    if (base + 2 < n) rowptr[base + 2] = excl + v0 + v1;
    if (base + 3 < n) rowptr[base + 3] = excl + v0 + v1 + v2;
    if (t == 255) bsum[blockIdx.x] = warp_tot[7] + inc;
}

__global__ void scan2_kernel(int* __restrict__ bsum, int nblk) {
    __shared__ int sh[1024];
    int t = threadIdx.x;
#pragma unroll
    for (int i = 0; i < 4; ++i) {
        int idx = t + i * 256;
        sh[idx] = (idx < nblk) ? bsum[idx] : 0;
    }
    __syncthreads();
    for (int off = 1; off < 1024; off <<= 1) {
        int v[4];
#pragma unroll
        for (int i = 0; i < 4; ++i) {
            int idx = t + i * 256;
            v[i] = (idx >= off) ? sh[idx - off] : 0;
        }
        __syncthreads();
#pragma unroll
        for (int i = 0; i < 4; ++i) sh[t + i * 256] += v[i];
        __syncthreads();
    }
#pragma unroll
    for (int i = 0; i < 4; ++i) {
        int idx = t + i * 256;
        if (idx < nblk) bsum[idx] = (idx == 0) ? 0 : sh[idx - 1];
    }
}

__global__ void scan3_kernel(int* __restrict__ rowptr, const int* __restrict__ bsum,
                             int n, int E) {
    int i = blockIdx.x * blockDim.x + threadIdx.x;
    if (i < n) rowptr[i] += bsum[i >> 10];
    if (i == 0) rowptr[n] = E;
}

__global__ void fill_kernel(const int* __restrict__ src, const int* __restrict__ dst,
                            const int* __restrict__ rowptr, int* __restrict__ cursor,
                            int* __restrict__ csr, int E) {
    int e = blockIdx.x * blockDim.x + threadIdx.x;
    if (e >= E) return;
    int d = dst[e];
    int pos = rowptr[d] + atomicAdd(&cursor[d], 1);
    csr[pos] = src[e];
}

// ---------------------------------------------------------------------------
// Gather: warp per node, 32 lanes x float4 = 128 features. Mean fused.
// ---------------------------------------------------------------------------
__global__ void __launch_bounds__(256)
gather_kernel(const float4* __restrict__ h4, const int* __restrict__ rowptr,
              const int* __restrict__ csr, const float* __restrict__ rdeg,
              float4* __restrict__ out4, int n) {
    int gw   = (blockIdx.x * blockDim.x + threadIdx.x) >> 5;
    int lane = threadIdx.x & 31;
    if (gw >= n) return;
    int s0 = rowptr[gw], s1 = rowptr[gw + 1];
    float4 acc = make_float4(0.f, 0.f, 0.f, 0.f);
    int j = s0;
    for (; j + 4 <= s1; j += 4) {
        int i0 = __ldg(&csr[j]);
        int i1 = __ldg(&csr[j + 1]);
        int i2 = __ldg(&csr[j + 2]);
        int i3 = __ldg(&csr[j + 3]);
        float4 a = h4[(size_t)i0 * 32 + lane];
        float4 b = h4[(size_t)i1 * 32 + lane];
        float4 c = h4[(size_t)i2 * 32 + lane];
        float4 d = h4[(size_t)i3 * 32 + lane];
        acc.x += a.x + b.x + c.x + d.x;
        acc.y += a.y + b.y + c.y + d.y;
        acc.z += a.z + b.z + c.z + d.z;
        acc.w += a.w + b.w + c.w + d.w;
    }
    for (; j < s1; ++j) {
        int i0 = __ldg(&csr[j]);
        float4 a = h4[(size_t)i0 * 32 + lane];
        acc.x += a.x; acc.y += a.y; acc.z += a.z; acc.w += a.w;
    }
    float rd = rdeg[gw];
    acc.x *= rd; acc.y *= rd; acc.z *= rd; acc.w *= rd;
    out4[(size_t)gw * 32 + lane] = acc;
}

// ---------------------------------------------------------------------------
// Double-buffered tiled fp32 GEMM, LDS.128 fragments, fused epilogue.
//   C[N,BN] = epi( A[N,KTOT] @ W[KTOT,BN] + bias ), DUAL splits A/W at K0.
// Block tile 128 x BN, thread tile 8 x (BN/16), 256 threads.
// ---------------------------------------------------------------------------
#define BM 128
#define BK 16

template<int KTOT, int BN, int K0, bool DUAL, bool RELU, bool AFF>
__global__ void __launch_bounds__(256, 2)
gemm_kernel(const float* __restrict__ A0, const float* __restrict__ A1,
            const float* __restrict__ W0, const float* __restrict__ W1,
            const float* __restrict__ bias,
            const float* __restrict__ gamma, const float* __restrict__ beta,
            float* __restrict__ C, int Nrows)
{
    constexpr int TM  = 8;
    constexpr int TN  = BN / 16;              // 8 or 4
    constexpr int K1  = KTOT - K0;
    constexpr int NT  = KTOT / BK;
    constexpr int F4R   = BN / 4;
    constexpr int B_PER = (BK * BN / 4) / 256;

    __shared__ float As[2][BK][BM];
    __shared__ float Bs[2][BK][BN];

    const int tid  = threadIdx.x;
    const int row0 = blockIdx.x * BM;
    const int trow = tid >> 4;
    const int tcol = tid & 15;

    const int ar_r0 = tid >> 2;
    const int ar_c  = (tid & 3) * 4;

    float acc[TM][TN];
#pragma unroll
    for (int i = 0; i < TM; ++i)
#pragma unroll
        for (int j = 0; j < TN; ++j) acc[i][j] = 0.0f;

    float4 ar[2];
    float4 br[B_PER];

    auto load_tile = [&](int kt) {
#pragma unroll
        for (int i = 0; i < 2; ++i) {
            int r    = ar_r0 + i * 64;
            int grow = row0 + r;
            int gk   = kt * BK + ar_c;
            float4 v = make_float4(0.f, 0.f, 0.f, 0.f);
            if (grow < Nrows) {
                if (!DUAL || gk < K0)
                    v = *(const float4*)(A0 + (size_t)grow * K0 + gk);
                else if constexpr (DUAL)
                    v = *(const float4*)(A1 + (size_t)grow * K1 + (gk - K0));
            }
            ar[i] = v;
        }
#pragma unroll
        for (int i = 0; i < B_PER; ++i) {
            int f  = tid + i * 256;
            int kk = f / F4R;
            int c4 = (f % F4R) * 4;
            int gk = kt * BK + kk;
            const float* Wp;
            if (!DUAL || gk < K0) Wp = W0 + (size_t)gk * BN + c4;
            else                  Wp = W1 + (size_t)(gk - K0) * BN + c4;
            br[i] = *(const float4*)Wp;
        }
    };

    auto store_tile = [&](int buf) {
#pragma unroll
        for (int i = 0; i < 2; ++i) {
            int r = ar_r0 + i * 64;
            As[buf][ar_c + 0][r] = ar[i].x;
            As[buf][ar_c + 1][r] = ar[i].y;
            As[buf][ar_c + 2][r] = ar[i].z;
            As[buf][ar_c + 3][r] = ar[i].w;
        }
#pragma unroll
        for (int i = 0; i < B_PER; ++i) {
            int f  = tid + i * 256;
            int kk = f / F4R;
            int c4 = (f % F4R) * 4;
            *(float4*)&Bs[buf][kk][c4] = br[i];
        }
    };

    load_tile(0);
    store_tile(0);
    __syncthreads();

    for (int kt = 0; kt < NT; ++kt) {
        const int cur = kt & 1;
        if (kt + 1 < NT) load_tile(kt + 1);

#pragma unroll
        for (int kk = 0; kk < BK; ++kk) {
            // LDS.128 fragment reads — conflict-free
            float a[TM], b[TN];
#pragma unroll
            for (int v = 0; v < TM / 4; ++v)
                *(float4*)&a[v * 4] = *(const float4*)&As[cur][kk][trow * TM + v * 4];
#pragma unroll
            for (int v = 0; v < TN / 4; ++v)
                *(float4*)&b[v * 4] = *(const float4*)&Bs[cur][kk][tcol * TN + v * 4];
#pragma unroll
            for (int i = 0; i < TM; ++i)
#pragma unroll
                for (int j = 0; j < TN; ++j)
                    acc[i][j] += a[i] * b[j];
        }

        if (kt + 1 < NT) store_tile(cur ^ 1);
        __syncthreads();
    }

    // epilogue: bias (+ BN affine) (+ relu), vectorized STG.128
    float scale[TN], shift[TN];
#pragma unroll
    for (int j = 0; j < TN; ++j) {
        int col  = tcol * TN + j;
        float bi = bias[col];
        if constexpr (AFF) {
            scale[j] = gamma[col] * rsqrtf(1.0f + 1e-5f);
            shift[j] = scale[j] * bi + beta[col];   // (v+bi)*sc+be = v*sc + (bi*sc+be)
        } else {
            scale[j] = 1.0f;
            shift[j] = bi;
        }
    }
#pragma unroll
    for (int i = 0; i < TM; ++i) {
        int grow = row0 + trow * TM + i;
        if (grow >= Nrows) continue;
        float o[TN];
#pragma unroll
        for (int j = 0; j < TN; ++j) {
            float v = acc[i][j] * scale[j] + shift[j];
            if constexpr (RELU) v = fmaxf(v, 0.0f);
            o[j] = v;
        }
        float* Cp = C + (size_t)grow * BN + tcol * TN;
#pragma unroll
        for (int v = 0; v < TN / 4; ++v)
            *(float4*)(Cp + v * 4) = *(const float4*)&o[v * 4];
    }
}

// ---------------------------------------------------------------------------
// Host launcher
// ---------------------------------------------------------------------------
extern "C" void kernel_launch(void* const* d_in, const int* in_sizes, int n_in,
                              void* d_out, int out_size)
{
    const float* x     = (const float*)d_in[0];
    const int*   eidx  = (const int*)  d_in[1];
    const float* w_in  = (const float*)d_in[2];
    const float* b_in  = (const float*)d_in[3];
    const float* w_l1  = (const float*)d_in[4];
    const float* b_l1  = (const float*)d_in[5];
    const float* w_r1  = (const float*)d_in[6];
    const float* g1    = (const float*)d_in[7];
    const float* be1   = (const float*)d_in[8];
    const float* w_l2  = (const float*)d_in[9];
    const float* b_l2  = (const float*)d_in[10];
    const float* w_r2  = (const float*)d_in[11];
    const float* g2    = (const float*)d_in[12];
    const float* be2   = (const float*)d_in[13];
    const float* w_out = (const float*)d_in[14];
    const float* b_out = (const float*)d_in[15];
    float* out = (float*)d_out;

    const int N = in_sizes[0] / 256;
    const int E = in_sizes[1] / 2;
    const int* src = eidx;
    const int* dst = eidx + E;

    float *bufA, *bufB, *agg, *rdeg;
    int *degi, *cursor, *rowptr, *csr, *bsum;
    cudaGetSymbolAddress((void**)&bufA,   g_bufA);
    cudaGetSymbolAddress((void**)&bufB,   g_bufB);
    cudaGetSymbolAddress((void**)&agg,    g_agg);
    cudaGetSymbolAddress((void**)&rdeg,   g_rdeg);
    cudaGetSymbolAddress((void**)&degi,   g_degi);
    cudaGetSymbolAddress((void**)&cursor, g_cursor);
    cudaGetSymbolAddress((void**)&rowptr, g_rowptr);
    cudaGetSymbolAddress((void**)&csr,    g_csr);
    cudaGetSymbolAddress((void**)&bsum,   g_bsum);

    const int nBlocks    = (N + 255) / 256;
    const int eBlocks    = (E + 255) / 256;
    const int gemmBlocks = (N + BM - 1) / BM;
    const int scanBlocks = (N + 1023) / 1024;
    const int gatherBlocks = (int)(((long long)N * 32 + 255) / 256);

    // ---- CSR build ----
    zero_int_kernel<<<nBlocks, 256>>>(degi, cursor, N);
    degi_kernel<<<eBlocks, 256>>>(dst, degi, E);
    rdeg_kernel<<<nBlocks, 256>>>(degi, rdeg, N);
    scan1_kernel<<<scanBlocks, 256>>>(degi, rowptr, bsum, N);
    scan2_kernel<<<1, 256>>>(bsum, scanBlocks);
    scan3_kernel<<<nBlocks, 256>>>(rowptr, bsum, N, E);
    fill_kernel<<<eBlocks, 256>>>(src, dst, rowptr, cursor, csr, E);

    // ---- input layer: bufA = relu(x @ w_in + b_in) ----
    gemm_kernel<256, 128, 256, false, true, false><<<gemmBlocks, 256>>>(
        x, nullptr, w_in, nullptr, b_in, nullptr, nullptr, bufA, N);

    // ---- SAGE layer 1 ----
    gather_kernel<<<gatherBlocks, 256>>>((const float4*)bufA, rowptr, csr, rdeg,
                                         (float4*)agg, N);
    gemm_kernel<256, 128, 128, true, true, true><<<gemmBlocks, 256>>>(
        agg, bufA, w_l1, w_r1, b_l1, g1, be1, bufB, N);

    // ---- SAGE layer 2 ----
    gather_kernel<<<gatherBlocks, 256>>>((const float4*)bufB, rowptr, csr, rdeg,
                                         (float4*)agg, N);
    gemm_kernel<256, 128, 128, true, true, true><<<gemmBlocks, 256>>>(
        agg, bufB, w_l2, w_r2, b_l2, g2, be2, bufA, N);

    // ---- output layer ----
    gemm_kernel<128, 64, 128, false, false, false><<<gemmBlocks, 256>>>(
        bufA, nullptr, w_out, nullptr, b_out, nullptr, nullptr, out, N);
}

// round 7
// speedup vs baseline: 3.9484x; 1.7616x over previous
#include <cuda_runtime.h>
#include <cuda_bf16.h>
#include <cstddef>
#include <cstdint>

// ---------------------------------------------------------------------------
// GNN: relu(x@W_in+b); 2x SAGEConv(mean) + BN(eval) + relu; out GEMM.
// N=100000, E=1.6M, D_IN=256, H=128, D_OUT=64, fp32 in/out.
//
// R6: tcgen05 PTX is rejected (harness PTX stage targets compute_103).
// GEMMs use mma.sync m16n8k16 bf16 (HMMA) with split precision:
//   a = a_hi + a_lo; C = Ah*Bh + Ah*Bl + Al*Bh   (rel err ~1e-5)
// Weights pre-transposed+split once per launch; fp32->bf16 conversion fused
// into smem staging; double-buffered; fused bias/BN/ReLU epilogue.
// CSR build + warp-per-node gather unchanged.
// ---------------------------------------------------------------------------

#define MAX_N 100000
#define MAX_E 1600000
#define HID   128

__device__ float g_bufA[(size_t)MAX_N * HID];
__device__ float g_bufB[(size_t)MAX_N * HID];
__device__ float g_agg [(size_t)MAX_N * HID];
__device__ float g_rdeg[MAX_N];
__device__ int   g_degi  [MAX_N];
__device__ int   g_cursor[MAX_N];
__device__ int   g_rowptr[MAX_N + 1];
__device__ int   g_csr   [MAX_E];
__device__ int   g_bsum  [1024];
// weight scratch: [BN, Ktot] bf16, hi/lo split, one pair per GEMM
__device__ __nv_bfloat16 g_wth[4][128 * 256];
__device__ __nv_bfloat16 g_wtl[4][128 * 256];

// ---------------------------------------------------------------------------
// helpers
// ---------------------------------------------------------------------------
__device__ __forceinline__ uint32_t smem_u32(const void* p) {
    uint32_t a;
    asm("{ .reg .u64 t; cvta.to.shared.u64 t, %1; cvt.u32.u64 %0, t; }"
        : "=r"(a) : "l"(p));
    return a;
}

__device__ __forceinline__ void ldsm_x4(uint32_t* r, uint32_t addr) {
    asm volatile("ldmatrix.sync.aligned.m8n8.x4.shared.b16 {%0,%1,%2,%3}, [%4];"
                 : "=r"(r[0]), "=r"(r[1]), "=r"(r[2]), "=r"(r[3]) : "r"(addr));
}

__device__ __forceinline__ void mma_bf16(float* c, const uint32_t* a, const uint32_t* b) {
    asm volatile("mma.sync.aligned.m16n8k16.row.col.f32.bf16.bf16.f32 "
                 "{%0,%1,%2,%3}, {%4,%5,%6,%7}, {%8,%9}, {%0,%1,%2,%3};"
                 : "+f"(c[0]), "+f"(c[1]), "+f"(c[2]), "+f"(c[3])
                 : "r"(a[0]), "r"(a[1]), "r"(a[2]), "r"(a[3]),
                   "r"(b[0]), "r"(b[1]));
}

__device__ __forceinline__ uint32_t pack2(float a, float b) {
    __nv_bfloat162 t = __floats2bfloat162_rn(a, b);
    return *reinterpret_cast<uint32_t*>(&t);
}

__device__ __forceinline__ void split8(const float4& v0, const float4& v1,
                                       uint4& hi, uint4& lo) {
    float f[8] = {v0.x, v0.y, v0.z, v0.w, v1.x, v1.y, v1.z, v1.w};
    float h[8], l[8];
#pragma unroll
    for (int i = 0; i < 8; ++i) {
        __nv_bfloat16 hb = __float2bfloat16_rn(f[i]);
        float hf = __bfloat162float(hb);
        h[i] = hf;
        l[i] = f[i] - hf;
    }
    hi.x = pack2(h[0], h[1]); hi.y = pack2(h[2], h[3]);
    hi.z = pack2(h[4], h[5]); hi.w = pack2(h[6], h[7]);
    lo.x = pack2(l[0], l[1]); lo.y = pack2(l[2], l[3]);
    lo.z = pack2(l[4], l[5]); lo.w = pack2(l[6], l[7]);
}

// ---------------------------------------------------------------------------
// CSR build (unchanged)
// ---------------------------------------------------------------------------
__global__ void zero_int_kernel(int* __restrict__ a, int* __restrict__ b, int n) {
    int i = blockIdx.x * blockDim.x + threadIdx.x;
    if (i < n) { a[i] = 0; b[i] = 0; }
}

__global__ void degi_kernel(const int* __restrict__ dst, int* __restrict__ deg, int E) {
    int e = blockIdx.x * blockDim.x + threadIdx.x;
    if (e < E) atomicAdd(&deg[dst[e]], 1);
}

__global__ void rdeg_kernel(const int* __restrict__ deg, float* __restrict__ rdeg, int n) {
    int i = blockIdx.x * blockDim.x + threadIdx.x;
    if (i < n) rdeg[i] = 1.0f / fmaxf((float)deg[i], 1.0f);
}

__global__ void scan1_kernel(const int* __restrict__ deg, int* __restrict__ rowptr,
                             int* __restrict__ bsum, int n) {
    __shared__ int warp_tot[8];
    int t = threadIdx.x, lane = t & 31, wid = t >> 5;
    int base = blockIdx.x * 1024 + t * 4;
    int v0 = (base + 0 < n) ? deg[base + 0] : 0;
    int v1 = (base + 1 < n) ? deg[base + 1] : 0;
    int v2 = (base + 2 < n) ? deg[base + 2] : 0;
    int v3 = (base + 3 < n) ? deg[base + 3] : 0;
    int tot = v0 + v1 + v2 + v3;

    int inc = tot;
#pragma unroll
    for (int off = 1; off < 32; off <<= 1) {
        int y = __shfl_up_sync(0xFFFFFFFF, inc, off);
        if (lane >= off) inc += y;
    }
    if (lane == 31) warp_tot[wid] = inc;
    __syncthreads();
    if (wid == 0) {
        int w = (lane < 8) ? warp_tot[lane] : 0;
        int wi = w;
#pragma unroll
        for (int off = 1; off < 8; off <<= 1) {
            int y = __shfl_up_sync(0xFFFFFFFF, wi, off);
            if (lane >= off) wi += y;
        }
        if (lane < 8) warp_tot[lane] = wi - w;
    }
    __syncthreads();
    int excl = warp_tot[wid] + inc - tot;

    if (base + 0 < n) rowptr[base + 0] = excl;
    if (base + 1 < n) rowptr[base + 1] = excl + v0;
    if (base + 2 < n) rowptr[base + 2] = excl + v0 + v1;
    if (base + 3 < n) rowptr[base + 3] = excl + v0 + v1 + v2;
    if (t == 255) bsum[blockIdx.x] = warp_tot[7] + inc;
}

__global__ void scan2_kernel(int* __restrict__ bsum, int nblk) {
    __shared__ int sh[1024];
    int t = threadIdx.x;
#pragma unroll
    for (int i = 0; i < 4; ++i) {
        int idx = t + i * 256;
        sh[idx] = (idx < nblk) ? bsum[idx] : 0;
    }
    __syncthreads();
    for (int off = 1; off < 1024; off <<= 1) {
        int v[4];
#pragma unroll
        for (int i = 0; i < 4; ++i) {
            int idx = t + i * 256;
            v[i] = (idx >= off) ? sh[idx - off] : 0;
        }
        __syncthreads();
#pragma unroll
        for (int i = 0; i < 4; ++i) sh[t + i * 256] += v[i];
        __syncthreads();
    }
#pragma unroll
    for (int i = 0; i < 4; ++i) {
        int idx = t + i * 256;
        if (idx < nblk) bsum[idx] = (idx == 0) ? 0 : sh[idx - 1];
    }
}

__global__ void scan3_kernel(int* __restrict__ rowptr, const int* __restrict__ bsum,
                             int n, int E) {
    int i = blockIdx.x * blockDim.x + threadIdx.x;
    if (i < n) rowptr[i] += bsum[i >> 10];
    if (i == 0) rowptr[n] = E;
}

__global__ void fill_kernel(const int* __restrict__ src, const int* __restrict__ dst,
                            const int* __restrict__ rowptr, int* __restrict__ cursor,
                            int* __restrict__ csr, int E) {
    int e = blockIdx.x * blockDim.x + threadIdx.x;
    if (e >= E) return;
    int d = dst[e];
    int pos = rowptr[d] + atomicAdd(&cursor[d], 1);
    csr[pos] = src[e];
}

// ---------------------------------------------------------------------------
// Gather: warp per node, 32 lanes x float4. Mean fused. (unchanged)
// ---------------------------------------------------------------------------
__global__ void __launch_bounds__(256)
gather_kernel(const float4* __restrict__ h4, const int* __restrict__ rowptr,
              const int* __restrict__ csr, const float* __restrict__ rdeg,
              float4* __restrict__ out4, int n) {
    int gw   = (blockIdx.x * blockDim.x + threadIdx.x) >> 5;
    int lane = threadIdx.x & 31;
    if (gw >= n) return;
    int s0 = rowptr[gw], s1 = rowptr[gw + 1];
    float4 acc = make_float4(0.f, 0.f, 0.f, 0.f);
    int j = s0;
    for (; j + 4 <= s1; j += 4) {
        int i0 = __ldg(&csr[j]);
        int i1 = __ldg(&csr[j + 1]);
        int i2 = __ldg(&csr[j + 2]);
        int i3 = __ldg(&csr[j + 3]);
        float4 a = h4[(size_t)i0 * 32 + lane];
        float4 b = h4[(size_t)i1 * 32 + lane];
        float4 c = h4[(size_t)i2 * 32 + lane];
        float4 d = h4[(size_t)i3 * 32 + lane];
        acc.x += a.x + b.x + c.x + d.x;
        acc.y += a.y + b.y + c.y + d.y;
        acc.z += a.z + b.z + c.z + d.z;
        acc.w += a.w + b.w + c.w + d.w;
    }
    for (; j < s1; ++j) {
        int i0 = __ldg(&csr[j]);
        float4 a = h4[(size_t)i0 * 32 + lane];
        acc.x += a.x; acc.y += a.y; acc.z += a.z; acc.w += a.w;
    }
    float rd = rdeg[gw];
    acc.x *= rd; acc.y *= rd; acc.z *= rd; acc.w *= rd;
    out4[(size_t)gw * 32 + lane] = acc;
}

// ---------------------------------------------------------------------------
// Weight prep: transpose + bf16 hi/lo split.  out[n*Ktot+k] = W[k,n]
// ---------------------------------------------------------------------------
__global__ void wprep_kernel(const float* __restrict__ W0, const float* __restrict__ W1,
                             int K0, int Ktot, int BNw,
                             __nv_bfloat16* __restrict__ oh,
                             __nv_bfloat16* __restrict__ ol) {
    int i = blockIdx.x * blockDim.x + threadIdx.x;
    if (i >= BNw * Ktot) return;
    int n = i / Ktot, k = i % Ktot;
    float w = (k < K0) ? W0[(size_t)k * BNw + n] : W1[(size_t)(k - K0) * BNw + n];
    __nv_bfloat16 h = __float2bfloat16_rn(w);
    oh[i] = h;
    ol[i] = __float2bfloat16_rn(w - __bfloat162float(h));
}

// ---------------------------------------------------------------------------
// HMMA split-bf16 GEMM.
//   C[Nrows, BN] = epi( A[Nrows, NC*32] @ W[NC*32, BN] + bias )
//   chunk c < NC0 reads A0 (stride sA0), else A1 (stride sA1).
// Block 128 x BN, 8 warps (4 x 2), warp tile 32 x BN/2, double-buffered.
// smem rows padded to 80B (conflict-free for staging stores and ldmatrix).
// ---------------------------------------------------------------------------
template<int BN, int NC, int NC0, bool RELU, bool AFF>
__global__ void __launch_bounds__(256, 1)
mma_gemm_kernel(const float* __restrict__ A0, const float* __restrict__ A1,
                int sA0, int sA1,
                const __nv_bfloat16* __restrict__ Wh,
                const __nv_bfloat16* __restrict__ Wl,
                const float* __restrict__ bias,
                const float* __restrict__ gamma,
                const float* __restrict__ beta,
                float* __restrict__ C, int Nrows)
{
    constexpr int KTOT   = NC * 32;
    constexpr int WN     = BN / 2;        // warp-tile N
    constexpr int NT8    = WN / 8;        // n8 accumulator tiles per warp
    constexpr int NT16   = WN / 16;       // n16 ldmatrix groups per warp
    constexpr int APITCH = 80;            // bytes per smem row (32 bf16 + pad)
    constexpr int ABYTES = 128 * APITCH;
    constexpr int BBYTES = BN * APITCH;
    constexpr int STAGE  = 2 * ABYTES + 2 * BBYTES;
    constexpr int BPER   = (BN * 4) / 256;   // B 16B-segs per thread

    extern __shared__ __align__(128) char smem[];
    const uint32_t sbase = smem_u32(smem);

    const int tid  = threadIdx.x;
    const int wid  = tid >> 5;
    const int lane = tid & 31;
    const int wm   = wid & 3;            // warp row (4)
    const int wn   = wid >> 2;           // warp col (2)
    const int row0 = blockIdx.x * 128;

    float acc[2][NT8][4];
#pragma unroll
    for (int mt = 0; mt < 2; ++mt)
#pragma unroll
        for (int nt = 0; nt < NT8; ++nt)
#pragma unroll
            for (int q = 0; q < 4; ++q) acc[mt][nt][q] = 0.0f;

    // register staging
    float4 af[2][2];
    uint4  bhr[BPER], blr[BPER];

    auto load_tile = [&](int c) {
        const float* Ap; int stride, koff;
        if (c < NC0) { Ap = A0; stride = sA0; koff = c * 32; }
        else         { Ap = A1; stride = sA1; koff = (c - NC0) * 32; }
#pragma unroll
        for (int s = 0; s < 2; ++s) {
            int f = tid + s * 256;              // 512 slots of 8 fp32
            int r = f >> 2, seg = f & 3;
            float4 v0 = make_float4(0.f, 0.f, 0.f, 0.f), v1 = v0;
            int grow = row0 + r;
            if (grow < Nrows) {
                const float* p = Ap + (size_t)grow * stride + koff + seg * 8;
                v0 = *(const float4*)p;
                v1 = *(const float4*)(p + 4);
            }
            af[s][0] = v0; af[s][1] = v1;
        }
#pragma unroll
        for (int s = 0; s < BPER; ++s) {
            int f = tid + s * 256;
            int n = f >> 2, seg = f & 3;
            size_t g = (size_t)n * KTOT + c * 32 + seg * 8;
            bhr[s] = *(const uint4*)(Wh + g);
            blr[s] = *(const uint4*)(Wl + g);
        }
    };

    auto store_tile = [&](int buf) {
        char* sp = smem + buf * STAGE;
#pragma unroll
        for (int s = 0; s < 2; ++s) {
            int f = tid + s * 256;
            int r = f >> 2, seg = f & 3;
            uint4 hi, lo;
            split8(af[s][0], af[s][1], hi, lo);
            uint32_t off = (uint32_t)(r * APITCH + seg * 16);
            *(uint4*)(sp + off)          = hi;
            *(uint4*)(sp + ABYTES + off) = lo;
        }
#pragma unroll
        for (int s = 0; s < BPER; ++s) {
            int f = tid + s * 256;
            int n = f >> 2, seg = f & 3;
            uint32_t off = (uint32_t)(n * APITCH + seg * 16);
            *(uint4*)(sp + 2 * ABYTES + off)          = bhr[s];
            *(uint4*)(sp + 2 * ABYTES + BBYTES + off) = blr[s];
        }
    };

    auto compute = [&](int buf) {
        const uint32_t aAh = sbase + buf * STAGE;
        const uint32_t aAl = aAh + ABYTES;
        const uint32_t aBh = aAh + 2 * ABYTES;
        const uint32_t aBl = aBh + BBYTES;
#pragma unroll
        for (int ks = 0; ks < 2; ++ks) {
            uint32_t ah[2][4], al[2][4];
#pragma unroll
            for (int mt = 0; mt < 2; ++mt) {
                uint32_t off = (uint32_t)((wm * 32 + mt * 16 + (lane & 15)) * APITCH
                                          + (ks * 16 + (lane >> 4) * 8) * 2);
                ldsm_x4(ah[mt], aAh + off);
                ldsm_x4(al[mt], aAl + off);
            }
#pragma unroll
            for (int nt2 = 0; nt2 < NT16; ++nt2) {
                uint32_t off = (uint32_t)((wn * WN + nt2 * 16 + (lane & 7)
                                           + ((lane >> 4) & 1) * 8) * APITCH
                                          + (ks * 16 + ((lane >> 3) & 1) * 8) * 2);
                uint32_t bh[4], bl[4];
                ldsm_x4(bh, aBh + off);
                ldsm_x4(bl, aBl + off);
#pragma unroll
                for (int mt = 0; mt < 2; ++mt) {
                    mma_bf16(acc[mt][nt2 * 2 + 0], ah[mt], bh + 0);
                    mma_bf16(acc[mt][nt2 * 2 + 0], ah[mt], bl + 0);
                    mma_bf16(acc[mt][nt2 * 2 + 0], al[mt], bh + 0);
                    mma_bf16(acc[mt][nt2 * 2 + 1], ah[mt], bh + 2);
                    mma_bf16(acc[mt][nt2 * 2 + 1], ah[mt], bl + 2);
                    mma_bf16(acc[mt][nt2 * 2 + 1], al[mt], bh + 2);
                }
            }
        }
    };

    load_tile(0);
    store_tile(0);
    __syncthreads();

#pragma unroll
    for (int c = 0; c < NC; ++c) {
        if (c + 1 < NC) load_tile(c + 1);
        compute(c & 1);
        if (c + 1 < NC) store_tile((c + 1) & 1);
        __syncthreads();
    }

    // ---- epilogue: C-fragment direct store + fused bias/BN/relu ----
    const int cb = wn * WN + 2 * (lane & 3);
    float2 scv[NT8], shv[NT8];
#pragma unroll
    for (int nt = 0; nt < NT8; ++nt) {
        int col = cb + nt * 8;
        float s0, h0, s1, h1;
        if constexpr (AFF) {
            s0 = __ldg(&gamma[col])     * rsqrtf(1.0f + 1e-5f);
            s1 = __ldg(&gamma[col + 1]) * rsqrtf(1.0f + 1e-5f);
            h0 = s0 * __ldg(&bias[col])     + __ldg(&beta[col]);
            h1 = s1 * __ldg(&bias[col + 1]) + __ldg(&beta[col + 1]);
        } else {
            s0 = 1.0f; s1 = 1.0f;
            h0 = __ldg(&bias[col]);
            h1 = __ldg(&bias[col + 1]);
        }
        scv[nt] = make_float2(s0, s1);
        shv[nt] = make_float2(h0, h1);
    }
    const int rbase = row0 + wm * 32 + (lane >> 2);
#pragma unroll
    for (int mt = 0; mt < 2; ++mt) {
#pragma unroll
        for (int h = 0; h < 2; ++h) {
            int row = rbase + mt * 16 + h * 8;
            if (row >= Nrows) continue;
            float* Cp = C + (size_t)row * BN;
#pragma unroll
            for (int nt = 0; nt < NT8; ++nt) {
                float v0 = acc[mt][nt][h * 2 + 0] * scv[nt].x + shv[nt].x;
                float v1 = acc[mt][nt][h * 2 + 1] * scv[nt].y + shv[nt].y;
                if constexpr (RELU) { v0 = fmaxf(v0, 0.0f); v1 = fmaxf(v1, 0.0f); }
                *(float2*)(Cp + cb + nt * 8) = make_float2(v0, v1);
            }
        }
    }
}

// ---------------------------------------------------------------------------
// Host launcher
// ---------------------------------------------------------------------------
extern "C" void kernel_launch(void* const* d_in, const int* in_sizes, int n_in,
                              void* d_out, int out_size)
{
    const float* x     = (const float*)d_in[0];
    const int*   eidx  = (const int*)  d_in[1];
    const float* w_in  = (const float*)d_in[2];
    const float* b_in  = (const float*)d_in[3];
    const float* w_l1  = (const float*)d_in[4];
    const float* b_l1  = (const float*)d_in[5];
    const float* w_r1  = (const float*)d_in[6];
    const float* g1    = (const float*)d_in[7];
    const float* be1   = (const float*)d_in[8];
    const float* w_l2  = (const float*)d_in[9];
    const float* b_l2  = (const float*)d_in[10];
    const float* w_r2  = (const float*)d_in[11];
    const float* g2    = (const float*)d_in[12];
    const float* be2   = (const float*)d_in[13];
    const float* w_out = (const float*)d_in[14];
    const float* b_out = (const float*)d_in[15];
    float* out = (float*)d_out;

    const int N = in_sizes[0] / 256;
    const int E = in_sizes[1] / 2;
    const int* src = eidx;
    const int* dst = eidx + E;

    float *bufA, *bufB, *agg, *rdeg;
    int *degi, *cursor, *rowptr, *csr, *bsum;
    __nv_bfloat16 *wth, *wtl;
    cudaGetSymbolAddress((void**)&bufA,   g_bufA);
    cudaGetSymbolAddress((void**)&bufB,   g_bufB);
    cudaGetSymbolAddress((void**)&agg,    g_agg);
    cudaGetSymbolAddress((void**)&rdeg,   g_rdeg);
    cudaGetSymbolAddress((void**)&degi,   g_degi);
    cudaGetSymbolAddress((void**)&cursor, g_cursor);
    cudaGetSymbolAddress((void**)&rowptr, g_rowptr);
    cudaGetSymbolAddress((void**)&csr,    g_csr);
    cudaGetSymbolAddress((void**)&bsum,   g_bsum);
    cudaGetSymbolAddress((void**)&wth,    g_wth);
    cudaGetSymbolAddress((void**)&wtl,    g_wtl);
    const int WSTR = 128 * 256;

    const int nBlocks    = (N + 255) / 256;
    const int eBlocks    = (E + 255) / 256;
    const int gemmBlocks = (N + 127) / 128;
    const int scanBlocks = (N + 1023) / 1024;
    const int gatherBlocks = (int)(((long long)N * 32 + 255) / 256);

    // dynamic smem: 2 stages x (2*A + 2*B), 80B-pitch rows
    const int S128 = 2 * (2 * 128 * 80 + 2 * 128 * 80);   // 81920
    const int S64  = 2 * (2 * 128 * 80 + 2 * 64 * 80);    // 61440
    cudaFuncSetAttribute(mma_gemm_kernel<128, 8, 8, true,  false>,
                         cudaFuncAttributeMaxDynamicSharedMemorySize, S128);
    cudaFuncSetAttribute(mma_gemm_kernel<128, 8, 4, true,  true >,
                         cudaFuncAttributeMaxDynamicSharedMemorySize, S128);
    cudaFuncSetAttribute(mma_gemm_kernel<64,  4, 4, false, false>,
                         cudaFuncAttributeMaxDynamicSharedMemorySize, S64);

    // ---- CSR build ----
    zero_int_kernel<<<nBlocks, 256>>>(degi, cursor, N);
    degi_kernel<<<eBlocks, 256>>>(dst, degi, E);
    rdeg_kernel<<<nBlocks, 256>>>(degi, rdeg, N);
    scan1_kernel<<<scanBlocks, 256>>>(degi, rowptr, bsum, N);
    scan2_kernel<<<1, 256>>>(bsum, scanBlocks);
    scan3_kernel<<<nBlocks, 256>>>(rowptr, bsum, N, E);
    fill_kernel<<<eBlocks, 256>>>(src, dst, rowptr, cursor, csr, E);

    // ---- weight prep (transpose + hi/lo split) ----
    wprep_kernel<<<(128 * 256 + 255) / 256, 256>>>(w_in, nullptr, 256, 256, 128,
                                                   wth + 0 * WSTR, wtl + 0 * WSTR);
    wprep_kernel<<<(128 * 256 + 255) / 256, 256>>>(w_l1, w_r1, 128, 256, 128,
                                                   wth + 1 * WSTR, wtl + 1 * WSTR);
    wprep_kernel<<<(128 * 256 + 255) / 256, 256>>>(w_l2, w_r2, 128, 256, 128,
                                                   wth + 2 * WSTR, wtl + 2 * WSTR);
    wprep_kernel<<<(64 * 128 + 255) / 256, 256>>>(w_out, nullptr, 128, 128, 64,
                                                  wth + 3 * WSTR, wtl + 3 * WSTR);

    // ---- input layer: bufA = relu(x @ w_in + b_in) ----
    mma_gemm_kernel<128, 8, 8, true, false><<<gemmBlocks, 256, S128>>>(
        x, nullptr, 256, 0, wth + 0 * WSTR, wtl + 0 * WSTR,
        b_in, nullptr, nullptr, bufA, N);

    // ---- SAGE layer 1 ----
    gather_kernel<<<gatherBlocks, 256>>>((const float4*)bufA, rowptr, csr, rdeg,
                                         (float4*)agg, N);
    mma_gemm_kernel<128, 8, 4, true, true><<<gemmBlocks, 256, S128>>>(
        agg, bufA, 128, 128, wth + 1 * WSTR, wtl + 1 * WSTR,
        b_l1, g1, be1, bufB, N);

    // ---- SAGE layer 2 ----
    gather_kernel<<<gatherBlocks, 256>>>((const float4*)bufB, rowptr, csr, rdeg,
                                         (float4*)agg, N);
    mma_gemm_kernel<128, 8, 4, true, true><<<gemmBlocks, 256, S128>>>(
        agg, bufB, 128, 128, wth + 2 * WSTR, wtl + 2 * WSTR,
        b_l2, g2, be2, bufA, N);

    // ---- output layer ----
    mma_gemm_kernel<64, 4, 4, false, false><<<gemmBlocks, 256, S64>>>(
        bufA, nullptr, 128, 0, wth + 3 * WSTR, wtl + 3 * WSTR,
        b_out, nullptr, nullptr, out, N);
}